// round 8
// baseline (speedup 1.0000x reference)
#include <cuda_runtime.h>
#include <cuda_fp16.h>
#include <cstdint>

#define N_  2
#define C_  128
#define D_  32
#define H_  64
#define W_  64
#define R_  256
#define PD  4
#define PH  7
#define PW  7
#define HW_ (H_ * W_)
#define DHW (D_ * H_ * W_)
#define NCELL (PH * PW)           // 49
#define NTASKB (NCELL * PD)       // 196 tasks per roi
#define OUTR (C_ * NTASKB)        // 25088 floats per roi
#define SSTRIDE 197               // stage row stride (words)
#define TAPCAP 68                 // 64 + 3 pad, rounded

// 64 MB static scratch: NDHWC features quantized to fp16
__device__ __half g_feat_t[(size_t)N_ * DHW * C_];

// ---------------------------------------------------------------------------
// Transpose NCDHW fp32 -> NDHWC fp16
// ---------------------------------------------------------------------------
__global__ void __launch_bounds__(256) transpose_ndhwc_h(const float* __restrict__ in,
                                                         __half* __restrict__ out) {
    __shared__ __half tile[32][66];
    const int n  = blockIdx.z;
    const int s0 = blockIdx.x * 32;
    const int c0 = blockIdx.y * 64;
    const int tx = threadIdx.x, ty = threadIdx.y;

    const float* ip = in  + (size_t)n * C_ * DHW;
    __half*      op = out + (size_t)n * DHW * C_;

#pragma unroll
    for (int i = 0; i < 64; i += 8)
        tile[tx][ty + i] = __float2half(ip[(size_t)(c0 + ty + i) * DHW + (s0 + tx)]);
    __syncthreads();
#pragma unroll
    for (int i = 0; i < 32; i += 8) {
        const int s = ty + i;
        __half2 v = *reinterpret_cast<const __half2*>(&tile[s][tx * 2]);
        *reinterpret_cast<__half2*>(&op[(size_t)(s0 + s) * C_ + c0 + tx * 2]) = v;
    }
}

// ---------------------------------------------------------------------------
// Per-axis separable taps
// ---------------------------------------------------------------------------
__device__ __forceinline__ void axis_taps(float c0, float c1, int size,
                                          int& base, float w[4]) {
    w[0] = w[1] = w[2] = w[3] = 0.0f;
    const float szf = (float)size;

    const bool v0 = (c0 >= -1.0f) && (c0 <= szf);
    float cc0 = fminf(fmaxf(c0, 0.0f), szf - 1.0f);
    const int lo0 = (int)floorf(cc0);
    const int hi0 = min(lo0 + 1, size - 1);
    const float f0 = cc0 - (float)lo0;

    const bool v1 = (c1 >= -1.0f) && (c1 <= szf);
    float cc1 = fminf(fmaxf(c1, 0.0f), szf - 1.0f);
    const int lo1 = (int)floorf(cc1);
    const int hi1 = min(lo1 + 1, size - 1);
    const float f1 = cc1 - (float)lo1;

    base = lo0;
    if (v0) { w[0]         += 1.0f - f0; w[hi0 - lo0] += f0; }
    if (v1) { w[lo1 - lo0] += 1.0f - f1; w[hi1 - lo0] += f1; }
}

__device__ __forceinline__ float sel4(int i, float a, float b, float c, float d) {
    return (i == 0) ? a : ((i == 1) ? b : ((i == 2) ? c : d));
}
__device__ __forceinline__ int sel4i(int i, int a, int b, int c, int d) {
    return (i == 0) ? a : ((i == 1) ? b : ((i == 2) ? c : d));
}

// ---------------------------------------------------------------------------
// Gather: one block per roi, 8 warps, warp handles 196/8 (cell,pd) tasks.
// Warp-cooperative tap compaction -> branch-free gather loop -> smem-staged
// coalesced output.
// ---------------------------------------------------------------------------
__global__ void __launch_bounds__(256, 1) roi3d_gather(const float* __restrict__ rois,
                                                       const uint2* __restrict__ fp,
                                                       float* __restrict__ out) {
    extern __shared__ float smem[];
    float* stage = smem;                                   // [128][SSTRIDE]
    int2*  taps  = (int2*)(smem + C_ * SSTRIDE);           // [8][TAPCAP]

    const int r    = blockIdx.x;
    const int tid  = threadIdx.x;
    const int wid  = tid >> 5;
    const int lane = tid & 31;

    const float* roi = rois + r * 7;
    const int   b  = (int)__ldg(roi);
    const float x1 = __ldg(roi + 1) * 0.25f, y1 = __ldg(roi + 2) * 0.25f;
    const float z1 = __ldg(roi + 3) * 0.25f;
    const float x2 = __ldg(roi + 4) * 0.25f, y2 = __ldg(roi + 5) * 0.25f;
    const float z2 = __ldg(roi + 6) * 0.25f;
    const float sz = fmaxf(z2 - z1, 1.0f) * (1.0f / (PD * 2));
    const float sy = fmaxf(y2 - y1, 1.0f) * (1.0f / (PH * 2));
    const float sx = fmaxf(x2 - x1, 1.0f) * (1.0f / (PW * 2));
    const int bbase = b * DHW;

    int2* wlist = taps + wid * TAPCAP;
    const uint2* __restrict__ fpl = fp + lane;   // lane = c4 channel group

    // lane's combo decomposition (fixed per lane across tasks)
    const int zi0 = lane >> 4,       zi1 = (lane + 32) >> 4;
    const int yi0 = (lane >> 2) & 3, yi1 = ((lane + 32) >> 2) & 3;
    const int xi  = lane & 3;

    for (int t = wid; t < NTASKB; t += 8) {
        const int cell = t >> 2;
        const int pd   = t & 3;
        const int ph   = cell / PW;
        const int pw   = cell - ph * PW;

        const float zc0 = z1 + ((float)(pd * 2) + 0.5f) * sz;
        const float yc0 = y1 + ((float)(ph * 2) + 0.5f) * sy;
        const float xc0 = x1 + ((float)(pw * 2) + 0.5f) * sx;

        int bz, by, bx;
        float wz[4], wy[4], wx[4];
        axis_taps(zc0, zc0 + sz, D_, bz, wz);
        axis_taps(yc0, yc0 + sy, H_, by, wy);
        axis_taps(xc0, xc0 + sx, W_, bx, wx);
        wz[0] *= 0.125f; wz[1] *= 0.125f; wz[2] *= 0.125f; wz[3] *= 0.125f;

        // uniform per-slot offsets (uint2 units: voxel * 32)
        const int zo0 = (bbase + bz * HW_) * 32;
        const int zo1 = zo0 + HW_ * 32, zo2 = zo0 + 2 * HW_ * 32, zo3 = zo0 + 3 * HW_ * 32;
        const int yo0 = by * W_ * 32;
        const int yo1 = yo0 + W_ * 32, yo2 = yo0 + 2 * W_ * 32, yo3 = yo0 + 3 * W_ * 32;
        const int xb  = bx * 32 + xi * 32;

        // ---- cooperative compaction: 64 combos over 32 lanes x 2 ----
        int nt = 0;
        {
            const float w0 = sel4(zi0, wz[0], wz[1], wz[2], wz[3])
                           * sel4(yi0, wy[0], wy[1], wy[2], wy[3]) * wx[xi];
            const int   o0 = sel4i(zi0, zo0, zo1, zo2, zo3)
                           + sel4i(yi0, yo0, yo1, yo2, yo3) + xb;
            unsigned bal = __ballot_sync(0xffffffffu, w0 != 0.0f);
            if (w0 != 0.0f) {
                int slot = __popc(bal & ((1u << lane) - 1u));
                wlist[slot] = make_int2(o0, __float_as_int(w0));
            }
            nt = __popc(bal);

            const float w1 = sel4(zi1, wz[0], wz[1], wz[2], wz[3])
                           * sel4(yi1, wy[0], wy[1], wy[2], wy[3]) * wx[xi];
            const int   o1 = sel4i(zi1, zo0, zo1, zo2, zo3)
                           + sel4i(yi1, yo0, yo1, yo2, yo3) + xb;
            unsigned bal1 = __ballot_sync(0xffffffffu, w1 != 0.0f);
            if (w1 != 0.0f) {
                int slot = nt + __popc(bal1 & ((1u << lane) - 1u));
                wlist[slot] = make_int2(o1, __float_as_int(w1));
            }
            nt += __popc(bal1);
        }
        if (lane < 3) wlist[nt + lane] = make_int2(0, 0);   // pad
        const int nt4 = (nt + 3) & ~3;
        __syncwarp();

        // ---- branch-free gather ----
        float4 acc = make_float4(0.0f, 0.0f, 0.0f, 0.0f);
        for (int j = 0; j < nt4; j += 4) {
            const int4 p0 = *reinterpret_cast<const int4*>(&wlist[j]);     // taps j, j+1
            const int4 p1 = *reinterpret_cast<const int4*>(&wlist[j + 2]); // taps j+2, j+3
            const uint2 v0 = __ldg(fpl + p0.x);
            const uint2 v1 = __ldg(fpl + p0.z);
            const uint2 v2 = __ldg(fpl + p1.x);
            const uint2 v3 = __ldg(fpl + p1.z);
            const float a0 = __int_as_float(p0.y);
            const float a1 = __int_as_float(p0.w);
            const float a2 = __int_as_float(p1.y);
            const float a3 = __int_as_float(p1.w);

            float2 f;
            f = __half22float2(*reinterpret_cast<const __half2*>(&v0.x));
            acc.x += f.x * a0; acc.y += f.y * a0;
            f = __half22float2(*reinterpret_cast<const __half2*>(&v0.y));
            acc.z += f.x * a0; acc.w += f.y * a0;
            f = __half22float2(*reinterpret_cast<const __half2*>(&v1.x));
            acc.x += f.x * a1; acc.y += f.y * a1;
            f = __half22float2(*reinterpret_cast<const __half2*>(&v1.y));
            acc.z += f.x * a1; acc.w += f.y * a1;
            f = __half22float2(*reinterpret_cast<const __half2*>(&v2.x));
            acc.x += f.x * a2; acc.y += f.y * a2;
            f = __half22float2(*reinterpret_cast<const __half2*>(&v2.y));
            acc.z += f.x * a2; acc.w += f.y * a2;
            f = __half22float2(*reinterpret_cast<const __half2*>(&v3.x));
            acc.x += f.x * a3; acc.y += f.y * a3;
            f = __half22float2(*reinterpret_cast<const __half2*>(&v3.y));
            acc.z += f.x * a3; acc.w += f.y * a3;
        }
        __syncwarp();

        // ---- stage at the OUTPUT column index: o = pd*NCELL + cell ----
        // (out layout is [r][c][pd][ph][pw]; previous round wrongly used t)
        const int ocol = pd * NCELL + cell;
        const int sb = lane * 4 * SSTRIDE + ocol;
        stage[sb]               = acc.x;
        stage[sb + SSTRIDE]     = acc.y;
        stage[sb + 2 * SSTRIDE] = acc.z;
        stage[sb + 3 * SSTRIDE] = acc.w;
    }

    __syncthreads();

    // ---- epilogue: coalesced copy stage[c][o] -> out[r][c][o] ----
    float* outr = out + (size_t)r * OUTR;
    for (int c = wid; c < C_; c += 8) {
        const float* srow = stage + c * SSTRIDE;
        float*       orow = outr + c * NTASKB;
        for (int e = lane; e < NTASKB; e += 32)
            orow[e] = srow[e];
    }
}

// ---------------------------------------------------------------------------
extern "C" void kernel_launch(void* const* d_in, const int* in_sizes, int n_in,
                              void* d_out, int out_size) {
    const float* features = (const float*)d_in[0];
    const float* rois     = (const float*)d_in[1];
    float*       out      = (float*)d_out;

    __half* feat_t = nullptr;
    cudaGetSymbolAddress((void**)&feat_t, g_feat_t);

    // 1) NCDHW fp32 -> NDHWC fp16
    dim3 tg(DHW / 32, C_ / 64, N_);
    dim3 tb(32, 8);
    transpose_ndhwc_h<<<tg, tb>>>(features, feat_t);

    // 2) Gather: block per roi
    const int smem_bytes = (C_ * SSTRIDE) * 4 + 8 * TAPCAP * 8;
    cudaFuncSetAttribute(roi3d_gather, cudaFuncAttributeMaxDynamicSharedMemorySize,
                         smem_bytes);
    roi3d_gather<<<R_, 256, smem_bytes>>>(rois, (const uint2*)feat_t, out);
}

// round 10
// speedup vs baseline: 1.4069x; 1.4069x over previous
#include <cuda_runtime.h>
#include <cuda_fp16.h>
#include <cstdint>

#define N_  2
#define C_  128
#define D_  32
#define H_  64
#define W_  64
#define R_  256
#define PD  4
#define PH  7
#define PW  7
#define HW_ (H_ * W_)
#define DHW (D_ * H_ * W_)
#define NCELL (PH * PW)           // 49
#define TAPCAP 68                 // 64 + pad

// 64 MB static scratch: NDHWC features quantized to fp16
__device__ __half g_feat_t[(size_t)N_ * DHW * C_];

// ---------------------------------------------------------------------------
// Transpose NCDHW fp32 -> NDHWC fp16
// ---------------------------------------------------------------------------
__global__ void __launch_bounds__(256) transpose_ndhwc_h(const float* __restrict__ in,
                                                         __half* __restrict__ out) {
    __shared__ __half tile[32][66];
    const int n  = blockIdx.z;
    const int s0 = blockIdx.x * 32;
    const int c0 = blockIdx.y * 64;
    const int tx = threadIdx.x, ty = threadIdx.y;

    const float* ip = in  + (size_t)n * C_ * DHW;
    __half*      op = out + (size_t)n * DHW * C_;

#pragma unroll
    for (int i = 0; i < 64; i += 8)
        tile[tx][ty + i] = __float2half(ip[(size_t)(c0 + ty + i) * DHW + (s0 + tx)]);
    __syncthreads();
#pragma unroll
    for (int i = 0; i < 32; i += 8) {
        const int s = ty + i;
        __half2 v = *reinterpret_cast<const __half2*>(&tile[s][tx * 2]);
        *reinterpret_cast<__half2*>(&op[(size_t)(s0 + s) * C_ + c0 + tx * 2]) = v;
    }
}

// ---------------------------------------------------------------------------
// Per-axis separable taps
// ---------------------------------------------------------------------------
__device__ __forceinline__ void axis_taps(float c0, float c1, int size,
                                          int& base, float w[4]) {
    w[0] = w[1] = w[2] = w[3] = 0.0f;
    const float szf = (float)size;

    const bool v0 = (c0 >= -1.0f) && (c0 <= szf);
    float cc0 = fminf(fmaxf(c0, 0.0f), szf - 1.0f);
    const int lo0 = (int)floorf(cc0);
    const int hi0 = min(lo0 + 1, size - 1);
    const float f0 = cc0 - (float)lo0;

    const bool v1 = (c1 >= -1.0f) && (c1 <= szf);
    float cc1 = fminf(fmaxf(c1, 0.0f), szf - 1.0f);
    const int lo1 = (int)floorf(cc1);
    const int hi1 = min(lo1 + 1, size - 1);
    const float f1 = cc1 - (float)lo1;

    base = lo0;
    if (v0) { w[0]         += 1.0f - f0; w[hi0 - lo0] += f0; }
    if (v1) { w[lo1 - lo0] += 1.0f - f1; w[hi1 - lo0] += f1; }
}

__device__ __forceinline__ float sel4(int i, float a, float b, float c, float d) {
    return (i == 0) ? a : ((i == 1) ? b : ((i == 2) ? c : d));
}
__device__ __forceinline__ int sel4i(int i, int a, int b, int c, int d) {
    return (i == 0) ? a : ((i == 1) ? b : ((i == 2) ? c : d));
}

// ---------------------------------------------------------------------------
// Gather: grid (R, NCELL), block (32, PD). Warp = one (cell, pd) task.
// Warp-cooperative ballot compaction into per-warp smem tap list,
// then branch-free unroll-4 gather. High occupancy (2.2KB smem, no stage).
// ---------------------------------------------------------------------------
__global__ void __launch_bounds__(32 * PD) roi3d_gather(const float* __restrict__ rois,
                                                        const uint2* __restrict__ fp,
                                                        float* __restrict__ out) {
    __shared__ int2 taps[PD][TAPCAP];

    const int r    = blockIdx.x;
    const int cell = blockIdx.y;
    const int ph   = cell / PW;
    const int pw   = cell - ph * PW;
    const int pd   = threadIdx.y;          // warp id = pd
    const int lane = threadIdx.x;

    const float* roi = rois + r * 7;
    const int   b  = (int)__ldg(roi);
    const float x1 = __ldg(roi + 1) * 0.25f, y1 = __ldg(roi + 2) * 0.25f;
    const float z1 = __ldg(roi + 3) * 0.25f;
    const float x2 = __ldg(roi + 4) * 0.25f, y2 = __ldg(roi + 5) * 0.25f;
    const float z2 = __ldg(roi + 6) * 0.25f;
    const float sz = fmaxf(z2 - z1, 1.0f) * (1.0f / (PD * 2));
    const float sy = fmaxf(y2 - y1, 1.0f) * (1.0f / (PH * 2));
    const float sx = fmaxf(x2 - x1, 1.0f) * (1.0f / (PW * 2));
    const int bbase = b * DHW;

    const float zc0 = z1 + ((float)(pd * 2) + 0.5f) * sz;
    const float yc0 = y1 + ((float)(ph * 2) + 0.5f) * sy;
    const float xc0 = x1 + ((float)(pw * 2) + 0.5f) * sx;

    int bz, by, bx;
    float wz[4], wy[4], wx[4];
    axis_taps(zc0, zc0 + sz, D_, bz, wz);
    axis_taps(yc0, yc0 + sy, H_, by, wy);
    axis_taps(xc0, xc0 + sx, W_, bx, wx);
    wz[0] *= 0.125f; wz[1] *= 0.125f; wz[2] *= 0.125f; wz[3] *= 0.125f;

    // lane's combo decomposition: combo = zi*16 + yi*4 + xi; lane -> combos lane, lane+32
    const int zi0 = lane >> 4,       zi1 = (lane + 32) >> 4;
    const int yi0 = (lane >> 2) & 3;                     // same for lane+32
    const int xi  = lane & 3;

    // uniform per-slot offsets (uint2 units: voxel * 32)
    const int zo0 = (bbase + bz * HW_) * 32;
    const int zo1 = zo0 + HW_ * 32, zo2 = zo0 + 2 * HW_ * 32, zo3 = zo0 + 3 * HW_ * 32;
    const int yo0 = by * W_ * 32;
    const int yo1 = yo0 + W_ * 32, yo2 = yo0 + 2 * W_ * 32, yo3 = yo0 + 3 * W_ * 32;
    const int xb  = bx * 32 + xi * 32;

    int2* wlist = taps[pd];

    // ---- cooperative compaction: 64 combos over 32 lanes x 2 ----
    int nt = 0;
    {
        const float wyx = sel4(yi0, wy[0], wy[1], wy[2], wy[3]) * wx[xi];
        const int   oyx = sel4i(yi0, yo0, yo1, yo2, yo3) + xb;

        const float w0 = sel4(zi0, wz[0], wz[1], wz[2], wz[3]) * wyx;
        const int   o0 = sel4i(zi0, zo0, zo1, zo2, zo3) + oyx;
        unsigned bal = __ballot_sync(0xffffffffu, w0 != 0.0f);
        if (w0 != 0.0f) {
            int slot = __popc(bal & ((1u << lane) - 1u));
            wlist[slot] = make_int2(o0, __float_as_int(w0));
        }
        nt = __popc(bal);

        const float w1 = sel4(zi1, wz[0], wz[1], wz[2], wz[3]) * wyx;
        const int   o1 = sel4i(zi1, zo0, zo1, zo2, zo3) + oyx;
        unsigned bal1 = __ballot_sync(0xffffffffu, w1 != 0.0f);
        if (w1 != 0.0f) {
            int slot = nt + __popc(bal1 & ((1u << lane) - 1u));
            wlist[slot] = make_int2(o1, __float_as_int(w1));
        }
        nt += __popc(bal1);
    }
    if (lane < 3) wlist[nt + lane] = make_int2(0, 0);   // pad
    const int nt4 = (nt + 3) & ~3;
    __syncwarp();

    // ---- branch-free gather (lane = channel group again) ----
    const uint2* __restrict__ fpl = fp + lane;
    float4 acc = make_float4(0.0f, 0.0f, 0.0f, 0.0f);

    for (int j = 0; j < nt4; j += 4) {
        const int4 p0 = *reinterpret_cast<const int4*>(&wlist[j]);     // taps j, j+1
        const int4 p1 = *reinterpret_cast<const int4*>(&wlist[j + 2]); // taps j+2, j+3
        const uint2 v0 = __ldg(fpl + p0.x);
        const uint2 v1 = __ldg(fpl + p0.z);
        const uint2 v2 = __ldg(fpl + p1.x);
        const uint2 v3 = __ldg(fpl + p1.z);
        const float a0 = __int_as_float(p0.y);
        const float a1 = __int_as_float(p0.w);
        const float a2 = __int_as_float(p1.y);
        const float a3 = __int_as_float(p1.w);

        float2 f;
        f = __half22float2(*reinterpret_cast<const __half2*>(&v0.x));
        acc.x += f.x * a0; acc.y += f.y * a0;
        f = __half22float2(*reinterpret_cast<const __half2*>(&v0.y));
        acc.z += f.x * a0; acc.w += f.y * a0;
        f = __half22float2(*reinterpret_cast<const __half2*>(&v1.x));
        acc.x += f.x * a1; acc.y += f.y * a1;
        f = __half22float2(*reinterpret_cast<const __half2*>(&v1.y));
        acc.z += f.x * a1; acc.w += f.y * a1;
        f = __half22float2(*reinterpret_cast<const __half2*>(&v2.x));
        acc.x += f.x * a2; acc.y += f.y * a2;
        f = __half22float2(*reinterpret_cast<const __half2*>(&v2.y));
        acc.z += f.x * a2; acc.w += f.y * a2;
        f = __half22float2(*reinterpret_cast<const __half2*>(&v3.x));
        acc.x += f.x * a3; acc.y += f.y * a3;
        f = __half22float2(*reinterpret_cast<const __half2*>(&v3.y));
        acc.z += f.x * a3; acc.w += f.y * a3;
    }

    // ---- direct stores (R4 pattern): out[r][c][pd][ph][pw], c = lane*4 ----
    const int ob = ((r * C_ + lane * 4) * PD + pd) * NCELL + cell;
    out[ob]                  = acc.x;
    out[ob + PD * NCELL]     = acc.y;
    out[ob + 2 * PD * NCELL] = acc.z;
    out[ob + 3 * PD * NCELL] = acc.w;
}

// ---------------------------------------------------------------------------
extern "C" void kernel_launch(void* const* d_in, const int* in_sizes, int n_in,
                              void* d_out, int out_size) {
    const float* features = (const float*)d_in[0];
    const float* rois     = (const float*)d_in[1];
    float*       out      = (float*)d_out;

    __half* feat_t = nullptr;
    cudaGetSymbolAddress((void**)&feat_t, g_feat_t);

    // 1) NCDHW fp32 -> NDHWC fp16
    dim3 tg(DHW / 32, C_ / 64, N_);
    dim3 tb(32, 8);
    transpose_ndhwc_h<<<tg, tb>>>(features, feat_t);

    // 2) Gather: warp per (cell, pd) task, high occupancy
    dim3 rg(R_, NCELL);
    dim3 rb(32, PD);
    roi3d_gather<<<rg, rb>>>(rois, (const uint2*)feat_t, out);
}